// round 6
// baseline (speedup 1.0000x reference)
#include <cuda_runtime.h>
#include <cuda_fp16.h>
#include <cstdint>
#include <math.h>

#define NROWS 16384
#define DDIM  64
#define BM    128
#define BN    128
#define NTILES   (NROWS / BN)     // 128
#define NCHUNKS  8
#define NTASKS   (NTILES * NCHUNKS)   // 1024
#define GRID_P   148
#define NTHR  512
#define SCALE_A 28.853900817779268f   // log2(e)/tau
#define LN2F    0.6931471805599453f
#define CBIG    12582912.0f           // 2^23 + 2^22

__device__ int8_t g_a8[NROWS * DDIM];     // round(z1raw * 127/max|row|)
__device__ int8_t g_b8[NROWS * DDIM];
__device__ float  g_ascale[NROWS];        // SCALE_A * max/(127*norm)
__device__ float  g_bscale[NROWS];        // max/(127*norm)
__device__ float  g_rowsum[NCHUNKS * NROWS];
__device__ float  g_pos[NROWS];
__device__ float  g_part1[64];

__device__ __forceinline__ uint32_t smem_u32(const void* p) {
    uint32_t a;
    asm("{ .reg .u64 t; cvta.to.shared.u64 t, %1; cvt.u32.u64 %0, t; }" : "=r"(a) : "l"(p));
    return a;
}
__device__ __forceinline__ float ex2f(float x) {
    float r; asm("ex2.approx.f32 %0, %1;" : "=f"(r) : "f"(x)); return r;
}
// 64B rows packed 2-per-128B line; p^line swizzle keeps ldmatrix conflict-free
__device__ __forceinline__ uint32_t sw64(int row, int chunk) {
    int line = row >> 1;
    int p = (((row & 1) << 2) | chunk) ^ (line & 7);
    return (uint32_t)(line * 128 + p * 16);
}
#define LDSM_X4(r0, r1, r2, r3, addr) \
    asm volatile("ldmatrix.sync.aligned.m8n8.x4.shared.b16 {%0,%1,%2,%3}, [%4];" \
        : "=r"(r0), "=r"(r1), "=r"(r2), "=r"(r3) : "r"(addr))
#define MMA16832_S8(d, a, b) \
    asm volatile("mma.sync.aligned.m16n8k32.row.col.s32.s8.s8.s32 " \
        "{%0,%1,%2,%3}, {%4,%5,%6,%7}, {%8,%9}, {%0,%1,%2,%3};" \
        : "+r"((d)[0]), "+r"((d)[1]), "+r"((d)[2]), "+r"((d)[3]) \
        : "r"((a)[0]), "r"((a)[1]), "r"((a)[2]), "r"((a)[3]), "r"((b)[0]), "r"((b)[1]))
#define CP_ASYNC16(dst, src) \
    asm volatile("cp.async.cg.shared.global [%0], [%1], 16;" :: "r"(dst), "l"(src))
#define CP_COMMIT()  asm volatile("cp.async.commit_group;" ::: "memory")
#define CP_WAIT(n)   asm volatile("cp.async.wait_group %0;" :: "n"(n) : "memory")

// ───────── Kernel 1: L2-normalize + per-row int8 quantize + scales ──────────
__global__ void normalize_kernel(const float* __restrict__ z1,
                                 const float* __restrict__ z2) {
    int warp = blockIdx.x * (blockDim.x >> 5) + (threadIdx.x >> 5);
    int lane = threadIdx.x & 31;
    int row  = warp * 2 + (lane >> 4);
    int l16  = lane & 15;

    const float* src; int8_t* dst; float* scl; float sc; int r;
    if (row < NROWS) { src = z1; dst = g_a8; scl = g_ascale; r = row;         sc = SCALE_A; }
    else             { src = z2; dst = g_b8; scl = g_bscale; r = row - NROWS; sc = 1.0f;    }

    float4 v = ((const float4*)(src + (size_t)r * DDIM))[l16];
    float ss = v.x * v.x + v.y * v.y + v.z * v.z + v.w * v.w;
    float mx = fmaxf(fmaxf(fabsf(v.x), fabsf(v.y)), fmaxf(fabsf(v.z), fabsf(v.w)));
    #pragma unroll
    for (int off = 8; off; off >>= 1) {
        ss += __shfl_xor_sync(0xffffffffu, ss, off);
        mx  = fmaxf(mx, __shfl_xor_sync(0xffffffffu, mx, off));
    }
    mx = fmaxf(mx, 1e-12f);
    float qs = 127.0f / mx;                    // raw-domain quant (norm cancels)
    int q0 = __float2int_rn(v.x * qs), q1 = __float2int_rn(v.y * qs);
    int q2 = __float2int_rn(v.z * qs), q3 = __float2int_rn(v.w * qs);
    uint32_t pk = (q0 & 0xFF) | ((q1 & 0xFF) << 8) | ((q2 & 0xFF) << 16) | ((uint32_t)q3 << 24);
    ((uint32_t*)(dst + (size_t)r * DDIM))[l16] = pk;
    if (l16 == 0)
        scl[r] = sc * mx / (127.0f * fmaxf(sqrtf(ss), 1e-12f));
}

// ── Kernel 2: persistent int8 mma.sync GEMM + rank-1 scale + exp2-sum ──────
// smem: B0 [0,8K) B1 [8K,16K) A [16K,24K) bs0 [24K,+512) bs1 [+512,+1K)
__global__ void __launch_bounds__(NTHR, 1) gemm_lse_kernel() {
    __shared__ __align__(128) char smem[25600];
    const uint32_t sb = smem_u32(smem);
    const int tid = threadIdx.x, lane = tid & 31, w = tid >> 5;
    const int wm = w >> 2, wn = w & 3;
    const int g = lane >> 3, r8 = lane & 7;
    const int q = lane >> 2, p4 = lane & 3;

    const int ar = tid >> 2, ac = tid & 3;     // one 16B chunk per thread

    for (int task = blockIdx.x; task < NTASKS; task += GRID_P) {
        const int rb = task >> 3, ck = task & 7, t0 = ck << 4;
        __syncthreads();                        // fence prev-task smem reuse

        // Stage A tile (cp.async, swizzled 64B rows)
        CP_ASYNC16(sb + 16384u + sw64(ar, ac), g_a8 + (size_t)rb * 8192 + tid * 16);
        CP_COMMIT();
        // Prefetch B tile t0 + its col scales -> buf0
        CP_ASYNC16(sb + sw64(ar, ac), g_b8 + (size_t)t0 * 8192 + tid * 16);
        if (tid < 32)
            CP_ASYNC16(sb + 24576u + (uint32_t)tid * 16,
                       (const char*)(g_bscale + t0 * BN) + tid * 16);
        CP_COMMIT();
        CP_WAIT(1);                             // A resident
        __syncthreads();

        // A fragments (s8 k32 via b16 ldmatrix view)
        uint32_t afr[2][2][4];
        #pragma unroll
        for (int mi = 0; mi < 2; mi++)
            #pragma unroll
            for (int ks = 0; ks < 2; ks++) {
                int m = wm * 32 + mi * 16 + (g & 1) * 8 + r8;
                int c = ks * 2 + (g >> 1);
                LDSM_X4(afr[mi][ks][0], afr[mi][ks][1], afr[mi][ks][2], afr[mi][ks][3],
                        sb + 16384u + sw64(m, c));
            }

        // Row scales (incl. log2e/tau) + FMA constants
        float cr[4], mCc[4];
        #pragma unroll
        for (int slot = 0; slot < 4; slot++) {
            int mi = slot >> 1, hi = slot & 1;
            cr[slot]  = g_ascale[rb * BM + wm * 32 + mi * 16 + hi * 8 + q];
            mCc[slot] = -CBIG * cr[slot];
        }

        float s[4] = {0.f, 0.f, 0.f, 0.f};

        #pragma unroll 1
        for (int it = 0; it < 16; it++) {
            const int t = t0 + it;
            const uint32_t bufb = sb + (uint32_t)((it & 1) << 13);
            const uint32_t bsb  = sb + 24576u + (uint32_t)((it & 1) << 9);
            if (it < 15) {
                const uint32_t nb  = sb + (uint32_t)(((it + 1) & 1) << 13);
                const uint32_t nbs = sb + 24576u + (uint32_t)(((it + 1) & 1) << 9);
                CP_ASYNC16(nb + sw64(ar, ac), g_b8 + (size_t)(t + 1) * 8192 + tid * 16);
                if (tid < 32)
                    CP_ASYNC16(nbs + (uint32_t)tid * 16,
                               (const char*)(g_bscale + (t + 1) * BN) + tid * 16);
                CP_COMMIT();
                CP_WAIT(1);
            } else {
                CP_WAIT(0);
            }
            __syncthreads();

            int c_[2][4][4];
            #pragma unroll
            for (int mi = 0; mi < 2; mi++)
                #pragma unroll
                for (int ni = 0; ni < 4; ni++)
                    #pragma unroll
                    for (int j = 0; j < 4; j++) c_[mi][ni][j] = 0;

            #pragma unroll
            for (int ks = 0; ks < 2; ks++) {
                uint32_t b[4][2];
                #pragma unroll
                for (int p = 0; p < 2; p++) {
                    int n = wn * 32 + p * 16 + (g & 1) * 8 + r8;
                    int c = ks * 2 + (g >> 1);
                    LDSM_X4(b[2 * p][0], b[2 * p + 1][0], b[2 * p][1], b[2 * p + 1][1],
                            bufb + sw64(n, c));
                }
                #pragma unroll
                for (int mi = 0; mi < 2; mi++)
                    #pragma unroll
                    for (int ni = 0; ni < 4; ni++)
                        MMA16832_S8(c_[mi][ni], afr[mi][ks], b[ni]);
            }

            // Col scales for this tile (staged in smem)
            float2 ds[4];
            #pragma unroll
            for (int ni = 0; ni < 4; ni++)
                ds[ni] = ((const float2*)(smem + (bsb - sb)))[wn * 16 + ni * 4 + p4];

            // Epilogue: s32->f32 bit trick (alu/fma), rank-1 scale, ex2, sum
            #pragma unroll
            for (int mi = 0; mi < 2; mi++)
                #pragma unroll
                for (int ni = 0; ni < 4; ni++) {
                    const int* cc = c_[mi][ni];
                    float f0 = __int_as_float(cc[0] + 0x4B400000);
                    float f1 = __int_as_float(cc[1] + 0x4B400000);
                    float f2 = __int_as_float(cc[2] + 0x4B400000);
                    float f3 = __int_as_float(cc[3] + 0x4B400000);
                    float u0 = fmaf(f0, cr[mi * 2],     mCc[mi * 2]);
                    float u1 = fmaf(f1, cr[mi * 2],     mCc[mi * 2]);
                    float u2 = fmaf(f2, cr[mi * 2 + 1], mCc[mi * 2 + 1]);
                    float u3 = fmaf(f3, cr[mi * 2 + 1], mCc[mi * 2 + 1]);
                    s[mi * 2]     += ex2f(u0 * ds[ni].x) + ex2f(u1 * ds[ni].y);
                    s[mi * 2 + 1] += ex2f(u2 * ds[ni].x) + ex2f(u3 * ds[ni].y);
                }

            // Diagonal capture (rare tile): recompute logits, unique writer
            if (t == rb && wm == wn) {
                #pragma unroll
                for (int mi = 0; mi < 2; mi++)
                    #pragma unroll
                    for (int ni = 0; ni < 4; ni++) {
                        const int* cc = c_[mi][ni];
                        int r0 = wm * 32 + mi * 16 + q, r1 = r0 + 8;
                        int cb = wn * 32 + ni * 8 + 2 * p4;
                        float f0 = __int_as_float(cc[0] + 0x4B400000);
                        float f1 = __int_as_float(cc[1] + 0x4B400000);
                        float f2 = __int_as_float(cc[2] + 0x4B400000);
                        float f3 = __int_as_float(cc[3] + 0x4B400000);
                        float l0 = fmaf(f0, cr[mi*2],   mCc[mi*2])   * ds[ni].x;
                        float l1 = fmaf(f1, cr[mi*2],   mCc[mi*2])   * ds[ni].y;
                        float l2 = fmaf(f2, cr[mi*2+1], mCc[mi*2+1]) * ds[ni].x;
                        float l3 = fmaf(f3, cr[mi*2+1], mCc[mi*2+1]) * ds[ni].y;
                        if (r0 == cb)     g_pos[rb * BM + r0] = l0;
                        if (r0 == cb + 1) g_pos[rb * BM + r0] = l1;
                        if (r1 == cb)     g_pos[rb * BM + r1] = l2;
                        if (r1 == cb + 1) g_pos[rb * BM + r1] = l3;
                    }
            }
            __syncthreads();
        }

        // Per-chunk row-sum reduction (overlay on B0 region)
        float* red = (float*)smem;              // [128][16] = 8192 B
        #pragma unroll
        for (int slot = 0; slot < 4; slot++) {
            int mi = slot >> 1, hi = slot & 1;
            int r = wm * 32 + mi * 16 + hi * 8 + q;
            red[r * 16 + wn * 4 + p4] = s[slot];
        }
        __syncthreads();
        if (tid < BM) {
            float tot = 0.f;
            #pragma unroll
            for (int i = 0; i < 16; i++) tot += red[tid * 16 + i];
            g_rowsum[ck * NROWS + rb * BM + tid] = tot;
        }
    }
}

// ───────────── Kernel 3a: per-row LSE merge + block partials ────────────────
__global__ void finalize1_kernel() {
    __shared__ float sh[256];
    int tid = threadIdx.x;
    int r = blockIdx.x * 256 + tid;
    float sum = 0.f;
    #pragma unroll
    for (int ck = 0; ck < NCHUNKS; ck++) sum += g_rowsum[ck * NROWS + r];
    sh[tid] = (log2f(sum) - g_pos[r]) * LN2F;
    __syncthreads();
    #pragma unroll
    for (int off = 128; off; off >>= 1) {
        if (tid < off) sh[tid] += sh[tid + off];
        __syncthreads();
    }
    if (tid == 0) g_part1[blockIdx.x] = sh[0];
}

// ───────────── Kernel 3b: final scalar ──────────────────────────────────────
__global__ void finalize2_kernel(float* __restrict__ out) {
    __shared__ float sh[64];
    int tid = threadIdx.x;
    sh[tid] = g_part1[tid];
    __syncthreads();
    #pragma unroll
    for (int off = 32; off; off >>= 1) {
        if (tid < off) sh[tid] += sh[tid + off];
        __syncthreads();
    }
    if (tid == 0) out[0] = sh[0] * (1.0f / (float)NROWS);
}

// ────────────────────────────────────────────────────────────────────────────
extern "C" void kernel_launch(void* const* d_in, const int* in_sizes, int n_in,
                              void* d_out, int out_size) {
    const float* z1 = (const float*)d_in[0];
    const float* z2 = (const float*)d_in[1];
    float* out = (float*)d_out;

    normalize_kernel<<<2048, 256>>>(z1, z2);
    gemm_lse_kernel<<<GRID_P, NTHR>>>();
    finalize1_kernel<<<64, 256>>>();
    finalize2_kernel<<<1, 64>>>(out);
}

// round 7
// speedup vs baseline: 2.3110x; 2.3110x over previous
#include <cuda_runtime.h>
#include <cuda_fp16.h>
#include <cstdint>
#include <math.h>

#define NROWS 16384
#define DDIM  64
#define BM    128
#define BN    128
#define NTILES   (NROWS / BN)     // 128
#define NCHUNKS  8                // 16 tiles per chunk
#define NTASKS   (NTILES * NCHUNKS)   // 1024
#define GRID_P   148
#define NTHR  512
#define SCALE_A 28.853900817779268f   // log2(e)/tau
#define LN2F    0.6931471805599453f
#define BIAS_H2 0xCA00CA00u           // packed half2(-12, -12)

__device__ __half g_ah[NROWS * DDIM];      // z1n * log2(e)/tau  [m][k]
__device__ __half g_bh[NROWS * DDIM];      // z2n               [n][k]
__device__ float  g_rowsum[NCHUNKS * NROWS];   // biased by 2^-12 (cancels)
__device__ float  g_pos[NROWS];                // biased logit (cancels)
__device__ unsigned g_done = 0;

__device__ __forceinline__ uint32_t smem_u32(const void* p) {
    uint32_t a;
    asm("{ .reg .u64 t; cvta.to.shared.u64 t, %1; cvt.u32.u64 %0, t; }" : "=r"(a) : "l"(p));
    return a;
}
__device__ __forceinline__ uint32_t ex2_h2(uint32_t x) {
    uint32_t r; asm("ex2.approx.f16x2 %0, %1;" : "=r"(r) : "r"(x)); return r;
}
__device__ __forceinline__ uint32_t hadd2u(uint32_t a, uint32_t b) {
    uint32_t r; asm("add.rn.f16x2 %0, %1, %2;" : "=r"(r) : "r"(a), "r"(b)); return r;
}
__device__ __forceinline__ float2 h2f(uint32_t u) {
    __half2 h = *reinterpret_cast<__half2*>(&u);
    return __half22float2(h);
}
#define LDSM_X4(r0, r1, r2, r3, addr) \
    asm volatile("ldmatrix.sync.aligned.m8n8.x4.shared.b16 {%0,%1,%2,%3}, [%4];" \
        : "=r"(r0), "=r"(r1), "=r"(r2), "=r"(r3) : "r"(addr))
#define MMA16816_F16(d, a, b) \
    asm volatile("mma.sync.aligned.m16n8k16.row.col.f16.f16.f16.f16 " \
        "{%0,%1}, {%2,%3,%4,%5}, {%6,%7}, {%0,%1};" \
        : "+r"((d)[0]), "+r"((d)[1]) \
        : "r"((a)[0]), "r"((a)[1]), "r"((a)[2]), "r"((a)[3]), "r"((b)[0]), "r"((b)[1]))
#define CP_ASYNC16(dst, src) \
    asm volatile("cp.async.cg.shared.global [%0], [%1], 16;" :: "r"(dst), "l"(src))
#define CP_COMMIT()  asm volatile("cp.async.commit_group;" ::: "memory")
#define CP_WAIT(n)   asm volatile("cp.async.wait_group %0;" :: "n"(n) : "memory")

// ─────────────── Kernel 1: L2-normalize + fp16 quantize + scale fold ────────
__global__ void normalize_kernel(const float* __restrict__ z1,
                                 const float* __restrict__ z2) {
    int warp = blockIdx.x * (blockDim.x >> 5) + (threadIdx.x >> 5);
    int lane = threadIdx.x & 31;
    int row  = warp * 2 + (lane >> 4);
    int l16  = lane & 15;

    const float* src; __half* dst; float scale; int r;
    if (row < NROWS) { src = z1; dst = g_ah; r = row;          scale = SCALE_A; }
    else             { src = z2; dst = g_bh; r = row - NROWS;  scale = 1.0f;    }

    float4 v = ((const float4*)(src + (size_t)r * DDIM))[l16];
    float ss = v.x * v.x + v.y * v.y + v.z * v.z + v.w * v.w;
    #pragma unroll
    for (int off = 8; off; off >>= 1)
        ss += __shfl_xor_sync(0xffffffffu, ss, off);
    float inv = scale / fmaxf(sqrtf(ss), 1e-12f);
    __half2 h0 = __floats2half2_rn(v.x * inv, v.y * inv);
    __half2 h1 = __floats2half2_rn(v.z * inv, v.w * inv);
    uint2 o = make_uint2(*(uint32_t*)&h0, *(uint32_t*)&h1);
    ((uint2*)(dst + (size_t)r * DDIM))[l16] = o;
}

// ── Kernel 2: persistent fp16 mma.sync GEMM + fp16 exp2 epilogue + finalize ─
// smem: B buf0 [0,16K), B buf1 [16K,32K), A stage [32K,48K)
__global__ void __launch_bounds__(NTHR, 1) gemm_lse_kernel(float* __restrict__ out) {
    __shared__ __align__(128) char smem[49152];
    const uint32_t sb = smem_u32(smem);
    const int tid = threadIdx.x, lane = tid & 31, w = tid >> 5;
    const int wm = w >> 2, wn = w & 3;
    const int g = lane >> 3, r8 = lane & 7;
    const int kg = g & 1;
    const int q = lane >> 2, p4 = lane & 3;

    uint32_t brow[2]; int bnlo[2];
    #pragma unroll
    for (int p = 0; p < 2; p++) {
        int n = wn * 32 + p * 16 + (g >> 1) * 8 + r8;
        brow[p] = (uint32_t)(n * 128);
        bnlo[p] = n & 7;
    }

    for (int task = blockIdx.x; task < NTASKS; task += GRID_P) {
        const int rb = task >> 3, ck = task & 7, t0 = ck << 4;

        {   // Stage A tile (swizzled)
            const uint4* asrc = (const uint4*)(g_ah + (size_t)rb * BM * DDIM);
            uint4* dstA = (uint4*)(smem + 32768);
            #pragma unroll
            for (int i = tid; i < 1024; i += NTHR) {
                int r = i >> 3, c = i & 7;
                dstA[r * 8 + (c ^ (r & 7))] = asrc[i];
            }
        }
        __syncthreads();

        uint32_t afr[2][4][4];
        #pragma unroll
        for (int mi = 0; mi < 2; mi++)
            #pragma unroll
            for (int ks = 0; ks < 4; ks++) {
                int m  = wm * 32 + mi * 16 + (g & 1) * 8 + r8;
                int kc = ks * 2 + (g >> 1);
                uint32_t addr = sb + 32768u + (uint32_t)(m * 128 + ((kc ^ (m & 7)) << 4));
                LDSM_X4(afr[mi][ks][0], afr[mi][ks][1], afr[mi][ks][2], afr[mi][ks][3], addr);
            }

        {   // Prefetch first B tile -> buf0
            const uint4* bs = (const uint4*)(g_bh + (size_t)t0 * BN * DDIM);
            #pragma unroll
            for (int i = tid; i < 1024; i += NTHR) {
                int r = i >> 3, c = i & 7;
                CP_ASYNC16(sb + (uint32_t)(r * 128 + ((c ^ (r & 7)) << 4)), bs + i);
            }
            CP_COMMIT();
        }

        float s[4] = {0.f, 0.f, 0.f, 0.f};
        uint32_t hacc[4] = {0u, 0u, 0u, 0u};

        #pragma unroll 1
        for (int it = 0; it < 16; it++) {
            const int t = t0 + it;
            const uint32_t bufb = sb + (uint32_t)((it & 1) << 14);
            if (it < 15) {
                const uint32_t nbuf = sb + (uint32_t)(((it + 1) & 1) << 14);
                const uint4* bs = (const uint4*)(g_bh + (size_t)(t + 1) * BN * DDIM);
                #pragma unroll
                for (int i = tid; i < 1024; i += NTHR) {
                    int r = i >> 3, c = i & 7;
                    CP_ASYNC16(nbuf + (uint32_t)(r * 128 + ((c ^ (r & 7)) << 4)), bs + i);
                }
                CP_COMMIT();
                CP_WAIT(1);
            } else {
                CP_WAIT(0);
            }
            __syncthreads();

            // Accumulators pre-biased to -12: MMA yields logit-12 directly.
            uint32_t c_[2][4][2];
            #pragma unroll
            for (int mi = 0; mi < 2; mi++)
                #pragma unroll
                for (int ni = 0; ni < 4; ni++) {
                    c_[mi][ni][0] = BIAS_H2; c_[mi][ni][1] = BIAS_H2;
                }

            #pragma unroll
            for (int ks = 0; ks < 4; ks++) {
                uint32_t b[4][2];
                #pragma unroll
                for (int p = 0; p < 2; p++) {
                    uint32_t addr = bufb + brow[p] +
                                    (uint32_t)((((ks * 2 + kg) ^ bnlo[p])) << 4);
                    LDSM_X4(b[2 * p][0], b[2 * p][1], b[2 * p + 1][0], b[2 * p + 1][1], addr);
                }
                #pragma unroll
                for (int mi = 0; mi < 2; mi++)
                    #pragma unroll
                    for (int ni = 0; ni < 4; ni++)
                        MMA16816_F16(c_[mi][ni], afr[mi][ks], b[ni]);
            }

            // Diagonal capture: store the BIASED logit (bias cancels in lse-pos)
            if (t == rb && wm == wn) {
                #pragma unroll
                for (int mi = 0; mi < 2; mi++)
                    #pragma unroll
                    for (int ni = 0; ni < 4; ni++) {
                        float2 f0 = h2f(c_[mi][ni][0]);
                        float2 f1 = h2f(c_[mi][ni][1]);
                        int r0 = wm * 32 + mi * 16 + q, r1 = r0 + 8;
                        int cb = wn * 32 + ni * 8 + 2 * p4;
                        if (r0 == cb)     g_pos[rb * BM + r0] = f0.x;
                        if (r0 == cb + 1) g_pos[rb * BM + r0] = f0.y;
                        if (r1 == cb)     g_pos[rb * BM + r1] = f1.x;
                        if (r1 == cb + 1) g_pos[rb * BM + r1] = f1.y;
                    }
            }

            // All-fp16 epilogue: ex2.f16x2 on raw MMA regs, HADD2 trees
            #pragma unroll
            for (int mi = 0; mi < 2; mi++)
                #pragma unroll
                for (int j = 0; j < 2; j++) {
                    uint32_t e0 = ex2_h2(c_[mi][0][j]);
                    uint32_t e1 = ex2_h2(c_[mi][1][j]);
                    uint32_t e2 = ex2_h2(c_[mi][2][j]);
                    uint32_t e3 = ex2_h2(c_[mi][3][j]);
                    uint32_t tsum = hadd2u(hadd2u(e0, e1), hadd2u(e2, e3));
                    hacc[mi * 2 + j] = hadd2u(hacc[mi * 2 + j], tsum);
                }
            if (it & 1) {                    // drain fp16 partials every 2 tiles
                #pragma unroll
                for (int slot = 0; slot < 4; slot++) {
                    float2 f = h2f(hacc[slot]);
                    s[slot] += f.x + f.y;
                    hacc[slot] = 0u;
                }
            }
            __syncthreads();
        }

        // Per-chunk row-sum reduction (overlay on dead buf0)
        float* red = (float*)smem;
        #pragma unroll
        for (int slot = 0; slot < 4; slot++) {
            int mi = slot >> 1, hi = slot & 1;
            int r = wm * 32 + mi * 16 + hi * 8 + q;
            red[r * 16 + wn * 4 + p4] = s[slot];
        }
        __syncthreads();
        if (tid < BM) {
            float tot = 0.f;
            #pragma unroll
            for (int i = 0; i < 16; i++) tot += red[tid * 16 + i];
            g_rowsum[ck * NROWS + rb * BM + tid] = tot;
        }
    }

    // ── Fused finalize: last CTA to arrive reduces all rows ──
    __syncthreads();
    int amLast = 0;
    if (tid == 0) {
        __threadfence();
        amLast = (atomicAdd(&g_done, 1u) == GRID_P - 1);
    }
    amLast = __syncthreads_or(amLast);
    if (amLast) {
        if (tid == 0) g_done = 0;            // reset for next graph replay
        float acc = 0.f;
        #pragma unroll 1
        for (int r = tid; r < NROWS; r += NTHR) {
            float sum = 0.f;
            #pragma unroll
            for (int ck = 0; ck < NCHUNKS; ck++) sum += g_rowsum[ck * NROWS + r];
            // both sum and pos carry the 2^-12 / -12 bias -> cancels exactly
            acc += log2f(sum) - g_pos[r];
        }
        float* red = (float*)smem;
        red[tid] = acc;
        __syncthreads();
        #pragma unroll
        for (int off = NTHR / 2; off; off >>= 1) {
            if (tid < off) red[tid] += red[tid + off];
            __syncthreads();
        }
        if (tid == 0) out[0] = red[0] * (LN2F / (float)NROWS);
    }
}

// ────────────────────────────────────────────────────────────────────────────
extern "C" void kernel_launch(void* const* d_in, const int* in_sizes, int n_in,
                              void* d_out, int out_size) {
    const float* z1 = (const float*)d_in[0];
    const float* z2 = (const float*)d_in[1];
    float* out = (float*)d_out;

    normalize_kernel<<<2048, 256>>>(z1, z2);
    gemm_lse_kernel<<<GRID_P, NTHR>>>(out);
}

// round 8
// speedup vs baseline: 2.9462x; 1.2749x over previous
#include <cuda_runtime.h>
#include <cuda_fp16.h>
#include <cstdint>
#include <math.h>

#define NROWS 16384
#define DDIM  64
#define BM    128
#define BN    64
#define NTILES   (NROWS / BN)     // 256
#define CHUNK    16               // tiles per task
#define NCHUNKS  (NTILES / CHUNK) // 16 chunks per rowblock
#define NTASKS   ((NROWS / BM) * NCHUNKS)   // 2048
#define GRID_P   296
#define NTHR  256
#define SCALE_A 28.853900817779268f   // log2(e)/tau
#define LN2F    0.6931471805599453f
#define BIAS_H2 0xCA00CA00u           // packed half2(-12, -12)

__device__ __half g_ah[NROWS * DDIM];      // z1n * log2(e)/tau  [m][k]
__device__ __half g_bh[NROWS * DDIM];      // z2n               [n][k]
__device__ float  g_rowsum[NCHUNKS * NROWS];   // biased by 2^-12 (cancels)
__device__ float  g_pos[NROWS];                // biased logit (cancels)
__device__ float  g_part1[64];

__device__ __forceinline__ uint32_t smem_u32(const void* p) {
    uint32_t a;
    asm("{ .reg .u64 t; cvta.to.shared.u64 t, %1; cvt.u32.u64 %0, t; }" : "=r"(a) : "l"(p));
    return a;
}
__device__ __forceinline__ uint32_t ex2_h2(uint32_t x) {
    uint32_t r; asm("ex2.approx.f16x2 %0, %1;" : "=r"(r) : "r"(x)); return r;
}
__device__ __forceinline__ uint32_t hadd2u(uint32_t a, uint32_t b) {
    uint32_t r; asm("add.rn.f16x2 %0, %1, %2;" : "=r"(r) : "r"(a), "r"(b)); return r;
}
__device__ __forceinline__ float2 h2f(uint32_t u) {
    __half2 h = *reinterpret_cast<__half2*>(&u);
    return __half22float2(h);
}
#define LDSM_X4(r0, r1, r2, r3, addr) \
    asm volatile("ldmatrix.sync.aligned.m8n8.x4.shared.b16 {%0,%1,%2,%3}, [%4];" \
        : "=r"(r0), "=r"(r1), "=r"(r2), "=r"(r3) : "r"(addr))
#define MMA16816_F16(d, a, b) \
    asm volatile("mma.sync.aligned.m16n8k16.row.col.f16.f16.f16.f16 " \
        "{%0,%1}, {%2,%3,%4,%5}, {%6,%7}, {%0,%1};" \
        : "+r"((d)[0]), "+r"((d)[1]) \
        : "r"((a)[0]), "r"((a)[1]), "r"((a)[2]), "r"((a)[3]), "r"((b)[0]), "r"((b)[1]))
#define CP_ASYNC16(dst, src) \
    asm volatile("cp.async.cg.shared.global [%0], [%1], 16;" :: "r"(dst), "l"(src))
#define CP_COMMIT()  asm volatile("cp.async.commit_group;" ::: "memory")
#define CP_WAIT(n)   asm volatile("cp.async.wait_group %0;" :: "n"(n) : "memory")

// ─────────────── Kernel 1: L2-normalize + fp16 quantize + scale fold ────────
__global__ void normalize_kernel(const float* __restrict__ z1,
                                 const float* __restrict__ z2) {
    int warp = blockIdx.x * (blockDim.x >> 5) + (threadIdx.x >> 5);
    int lane = threadIdx.x & 31;
    int row  = warp * 2 + (lane >> 4);
    int l16  = lane & 15;

    const float* src; __half* dst; float scale; int r;
    if (row < NROWS) { src = z1; dst = g_ah; r = row;          scale = SCALE_A; }
    else             { src = z2; dst = g_bh; r = row - NROWS;  scale = 1.0f;    }

    float4 v = ((const float4*)(src + (size_t)r * DDIM))[l16];
    float ss = v.x * v.x + v.y * v.y + v.z * v.z + v.w * v.w;
    #pragma unroll
    for (int off = 8; off; off >>= 1)
        ss += __shfl_xor_sync(0xffffffffu, ss, off);
    float inv = scale / fmaxf(sqrtf(ss), 1e-12f);
    __half2 h0 = __floats2half2_rn(v.x * inv, v.y * inv);
    __half2 h1 = __floats2half2_rn(v.z * inv, v.w * inv);
    uint2 o = make_uint2(*(uint32_t*)&h0, *(uint32_t*)&h1);
    ((uint2*)(dst + (size_t)r * DDIM))[l16] = o;
}

// ── Kernel 2: persistent fp16 GEMM + fp16 exp2 epilogue, 2 CTAs/SM ─────────
// smem: B buf0 [0,8K), B buf1 [8K,16K), A stage [16K,32K)
__global__ void __launch_bounds__(NTHR, 2) gemm_lse_kernel() {
    __shared__ __align__(128) char smem[32768];
    const uint32_t sb = smem_u32(smem);
    const int tid = threadIdx.x, lane = tid & 31, w = tid >> 5;
    const int wm = w >> 1, wn = w & 1;          // 4x2 warp grid, 32x32 tiles
    const int g = lane >> 3, r8 = lane & 7;
    const int kg = g & 1;
    const int q = lane >> 2, p4 = lane & 3;

    uint32_t brow[2]; int bnlo[2];
    #pragma unroll
    for (int p = 0; p < 2; p++) {
        int n = wn * 32 + p * 16 + (g >> 1) * 8 + r8;
        brow[p] = (uint32_t)(n * 128);
        bnlo[p] = n & 7;
    }

    for (int task = blockIdx.x; task < NTASKS; task += GRID_P) {
        const int rb = task >> 4, ck = task & 15, t0 = ck << 4;

        // Stage A tile (cp.async, swizzled): 128 rows x 128B
        {
            const uint4* asrc = (const uint4*)(g_ah + (size_t)rb * BM * DDIM);
            #pragma unroll
            for (int i = tid; i < 1024; i += NTHR) {
                int r = i >> 3, c = i & 7;
                CP_ASYNC16(sb + 16384u + (uint32_t)(r * 128 + ((c ^ (r & 7)) << 4)),
                           asrc + i);
            }
            CP_COMMIT();
        }
        // Prefetch B tile t0 -> buf0: 64 rows x 128B
        {
            const uint4* bs = (const uint4*)(g_bh + (size_t)t0 * BN * DDIM);
            #pragma unroll
            for (int i = tid; i < 512; i += NTHR) {
                int r = i >> 3, c = i & 7;
                CP_ASYNC16(sb + (uint32_t)(r * 128 + ((c ^ (r & 7)) << 4)), bs + i);
            }
            CP_COMMIT();
        }
        CP_WAIT(1);                             // A resident; B0 may be in flight
        __syncthreads();

        uint32_t afr[2][4][4];
        #pragma unroll
        for (int mi = 0; mi < 2; mi++)
            #pragma unroll
            for (int ks = 0; ks < 4; ks++) {
                int m  = wm * 32 + mi * 16 + (g & 1) * 8 + r8;
                int kc = ks * 2 + (g >> 1);
                uint32_t addr = sb + 16384u + (uint32_t)(m * 128 + ((kc ^ (m & 7)) << 4));
                LDSM_X4(afr[mi][ks][0], afr[mi][ks][1], afr[mi][ks][2], afr[mi][ks][3], addr);
            }

        float s[4] = {0.f, 0.f, 0.f, 0.f};
        uint32_t hacc[4] = {0u, 0u, 0u, 0u};

        #pragma unroll 1
        for (int it = 0; it < CHUNK; it++) {
            const int t = t0 + it;
            const uint32_t bufb = sb + (uint32_t)((it & 1) << 13);
            if (it < CHUNK - 1) {
                const uint32_t nbuf = sb + (uint32_t)(((it + 1) & 1) << 13);
                const uint4* bs = (const uint4*)(g_bh + (size_t)(t + 1) * BN * DDIM);
                #pragma unroll
                for (int i = tid; i < 512; i += NTHR) {
                    int r = i >> 3, c = i & 7;
                    CP_ASYNC16(nbuf + (uint32_t)(r * 128 + ((c ^ (r & 7)) << 4)), bs + i);
                }
                CP_COMMIT();
                CP_WAIT(1);
            } else {
                CP_WAIT(0);
            }
            __syncthreads();

            // Accumulators pre-biased to -12: MMA yields logit-12 directly.
            uint32_t c_[2][4][2];
            #pragma unroll
            for (int mi = 0; mi < 2; mi++)
                #pragma unroll
                for (int ni = 0; ni < 4; ni++) {
                    c_[mi][ni][0] = BIAS_H2; c_[mi][ni][1] = BIAS_H2;
                }

            #pragma unroll
            for (int ks = 0; ks < 4; ks++) {
                uint32_t b[4][2];
                #pragma unroll
                for (int p = 0; p < 2; p++) {
                    uint32_t addr = bufb + brow[p] +
                                    (uint32_t)((((ks * 2 + kg) ^ bnlo[p])) << 4);
                    LDSM_X4(b[2 * p][0], b[2 * p][1], b[2 * p + 1][0], b[2 * p + 1][1], addr);
                }
                #pragma unroll
                for (int mi = 0; mi < 2; mi++)
                    #pragma unroll
                    for (int ni = 0; ni < 4; ni++)
                        MMA16816_F16(c_[mi][ni], afr[mi][ks], b[ni]);
            }

            // Diagonal capture: rows rb*128+[0,128) x cols t*64+[0,64)
            if ((t >> 1) == rb) {
                const int coff = (t & 1) << 6;
                #pragma unroll
                for (int mi = 0; mi < 2; mi++)
                    #pragma unroll
                    for (int ni = 0; ni < 4; ni++) {
                        float2 f0 = h2f(c_[mi][ni][0]);
                        float2 f1 = h2f(c_[mi][ni][1]);
                        int r0 = wm * 32 + mi * 16 + q, r1 = r0 + 8;
                        int cb = coff + wn * 32 + ni * 8 + 2 * p4;
                        if (r0 == cb)     g_pos[rb * BM + r0] = f0.x;
                        if (r0 == cb + 1) g_pos[rb * BM + r0] = f0.y;
                        if (r1 == cb)     g_pos[rb * BM + r1] = f1.x;
                        if (r1 == cb + 1) g_pos[rb * BM + r1] = f1.y;
                    }
            }

            // All-fp16 epilogue: ex2.f16x2 on raw MMA regs, HADD2 trees
            #pragma unroll
            for (int mi = 0; mi < 2; mi++)
                #pragma unroll
                for (int j = 0; j < 2; j++) {
                    uint32_t e0 = ex2_h2(c_[mi][0][j]);
                    uint32_t e1 = ex2_h2(c_[mi][1][j]);
                    uint32_t e2 = ex2_h2(c_[mi][2][j]);
                    uint32_t e3 = ex2_h2(c_[mi][3][j]);
                    uint32_t tsum = hadd2u(hadd2u(e0, e1), hadd2u(e2, e3));
                    hacc[mi * 2 + j] = hadd2u(hacc[mi * 2 + j], tsum);
                }
            if (it & 1) {                    // drain fp16 partials every 2 tiles
                #pragma unroll
                for (int slot = 0; slot < 4; slot++) {
                    float2 f = h2f(hacc[slot]);
                    s[slot] += f.x + f.y;
                    hacc[slot] = 0u;
                }
            }
            __syncthreads();
        }

        // Per-chunk row-sum reduction (overlay on dead buf0): [128][8]
        float* red = (float*)smem;
        #pragma unroll
        for (int slot = 0; slot < 4; slot++) {
            int mi = slot >> 1, hi = slot & 1;
            int r = wm * 32 + mi * 16 + hi * 8 + q;
            red[r * 8 + wn * 4 + p4] = s[slot];
        }
        __syncthreads();
        if (tid < BM) {
            float tot = 0.f;
            #pragma unroll
            for (int i = 0; i < 8; i++) tot += red[tid * 8 + i];
            g_rowsum[ck * NROWS + rb * BM + tid] = tot;
        }
        __syncthreads();                     // red reads done before next task
    }
}

// ───────────── Kernel 3a: per-row LSE merge + block partials ────────────────
__global__ void finalize1_kernel() {
    __shared__ float sh[256];
    int tid = threadIdx.x;
    int r = blockIdx.x * 256 + tid;
    float sum = 0.f;
    #pragma unroll
    for (int ck = 0; ck < NCHUNKS; ck++) sum += g_rowsum[ck * NROWS + r];
    // both sum and pos carry the 2^-12 / -12 bias -> cancels exactly
    sh[tid] = (log2f(sum) - g_pos[r]) * LN2F;
    __syncthreads();
    #pragma unroll
    for (int off = 128; off; off >>= 1) {
        if (tid < off) sh[tid] += sh[tid + off];
        __syncthreads();
    }
    if (tid == 0) g_part1[blockIdx.x] = sh[0];
}

// ───────────── Kernel 3b: final scalar ──────────────────────────────────────
__global__ void finalize2_kernel(float* __restrict__ out) {
    __shared__ float sh[64];
    int tid = threadIdx.x;
    sh[tid] = g_part1[tid];
    __syncthreads();
    #pragma unroll
    for (int off = 32; off; off >>= 1) {
        if (tid < off) sh[tid] += sh[tid + off];
        __syncthreads();
    }
    if (tid == 0) out[0] = sh[0] * (1.0f / (float)NROWS);
}

// ────────────────────────────────────────────────────────────────────────────
extern "C" void kernel_launch(void* const* d_in, const int* in_sizes, int n_in,
                              void* d_out, int out_size) {
    const float* z1 = (const float*)d_in[0];
    const float* z2 = (const float*)d_in[1];
    float* out = (float*)d_out;

    normalize_kernel<<<2048, 256>>>(z1, z2);
    gemm_lse_kernel<<<GRID_P, NTHR>>>();
    finalize1_kernel<<<64, 256>>>();
    finalize2_kernel<<<1, 64>>>(out);
}

// round 9
// speedup vs baseline: 3.0624x; 1.0394x over previous
#include <cuda_runtime.h>
#include <cuda_fp16.h>
#include <cstdint>
#include <math.h>

#define NROWS 16384
#define DDIM  64
#define BM    128
#define BN    64
#define NTILES   (NROWS / BN)     // 256
#define CHUNK    16               // tiles per task
#define NCHUNKS  (NTILES / CHUNK) // 16 chunks per rowblock
#define NTASKS   ((NROWS / BM) * NCHUNKS)   // 2048
#define GRID_P   444
#define NTHR  256
#define SCALE_A 28.853900817779268f   // log2(e)/tau
#define LN2F    0.6931471805599453f
#define BIAS_H2 0xCA00CA00u           // packed half2(-12, -12)

__device__ __half g_ah[NROWS * DDIM];      // z1n * log2(e)/tau  [m][k]
__device__ __half g_bh[NROWS * DDIM];      // z2n               [n][k]
__device__ float  g_rowsum[NCHUNKS * NROWS];   // biased by 2^-12 (cancels)
__device__ float  g_pos[NROWS];                // biased logit (cancels)
__device__ float  g_part1[64];

__device__ __forceinline__ uint32_t smem_u32(const void* p) {
    uint32_t a;
    asm("{ .reg .u64 t; cvta.to.shared.u64 t, %1; cvt.u32.u64 %0, t; }" : "=r"(a) : "l"(p));
    return a;
}
__device__ __forceinline__ uint32_t ex2_h2(uint32_t x) {
    uint32_t r; asm("ex2.approx.f16x2 %0, %1;" : "=r"(r) : "r"(x)); return r;
}
__device__ __forceinline__ uint32_t hadd2u(uint32_t a, uint32_t b) {
    uint32_t r; asm("add.rn.f16x2 %0, %1, %2;" : "=r"(r) : "r"(a), "r"(b)); return r;
}
__device__ __forceinline__ float2 h2f(uint32_t u) {
    __half2 h = *reinterpret_cast<__half2*>(&u);
    return __half22float2(h);
}
#define LDSM_X4(r0, r1, r2, r3, addr) \
    asm volatile("ldmatrix.sync.aligned.m8n8.x4.shared.b16 {%0,%1,%2,%3}, [%4];" \
        : "=r"(r0), "=r"(r1), "=r"(r2), "=r"(r3) : "r"(addr))
#define MMA16816_F16(d, a, b) \
    asm volatile("mma.sync.aligned.m16n8k16.row.col.f16.f16.f16.f16 " \
        "{%0,%1}, {%2,%3,%4,%5}, {%6,%7}, {%0,%1};" \
        : "+r"((d)[0]), "+r"((d)[1]) \
        : "r"((a)[0]), "r"((a)[1]), "r"((a)[2]), "r"((a)[3]), "r"((b)[0]), "r"((b)[1]))
#define CP_ASYNC16(dst, src) \
    asm volatile("cp.async.cg.shared.global [%0], [%1], 16;" :: "r"(dst), "l"(src))
#define CP_COMMIT()  asm volatile("cp.async.commit_group;" ::: "memory")
#define CP_WAIT(n)   asm volatile("cp.async.wait_group %0;" :: "n"(n) : "memory")

// ─────────────── Kernel 1: L2-normalize + fp16 quantize + scale fold ────────
__global__ void normalize_kernel(const float* __restrict__ z1,
                                 const float* __restrict__ z2) {
    int warp = blockIdx.x * (blockDim.x >> 5) + (threadIdx.x >> 5);
    int lane = threadIdx.x & 31;
    int row  = warp * 2 + (lane >> 4);
    int l16  = lane & 15;

    const float* src; __half* dst; float scale; int r;
    if (row < NROWS) { src = z1; dst = g_ah; r = row;          scale = SCALE_A; }
    else             { src = z2; dst = g_bh; r = row - NROWS;  scale = 1.0f;    }

    float4 v = ((const float4*)(src + (size_t)r * DDIM))[l16];
    float ss = v.x * v.x + v.y * v.y + v.z * v.z + v.w * v.w;
    #pragma unroll
    for (int off = 8; off; off >>= 1)
        ss += __shfl_xor_sync(0xffffffffu, ss, off);
    float inv = scale / fmaxf(sqrtf(ss), 1e-12f);
    __half2 h0 = __floats2half2_rn(v.x * inv, v.y * inv);
    __half2 h1 = __floats2half2_rn(v.z * inv, v.w * inv);
    uint2 o = make_uint2(*(uint32_t*)&h0, *(uint32_t*)&h1);
    ((uint2*)(dst + (size_t)r * DDIM))[l16] = o;
}

// ── Kernel 2: persistent fp16 GEMM + fp16 exp2 epilogue, 3 CTAs/SM ─────────
// smem: B buf0 [0,8K), B buf1 [8K,16K), A stage [16K,32K)
__global__ void __launch_bounds__(NTHR, 3) gemm_lse_kernel() {
    __shared__ __align__(128) char smem[32768];
    const uint32_t sb = smem_u32(smem);
    const int tid = threadIdx.x, lane = tid & 31, w = tid >> 5;
    const int wm = w >> 1, wn = w & 1;          // 4x2 warp grid, 32x32 tiles
    const int g = lane >> 3, r8 = lane & 7;
    const int kg = g & 1;
    const int q = lane >> 2, p4 = lane & 3;

    uint32_t brow[2]; int bnlo[2];
    #pragma unroll
    for (int p = 0; p < 2; p++) {
        int n = wn * 32 + p * 16 + (g >> 1) * 8 + r8;
        brow[p] = (uint32_t)(n * 128);
        bnlo[p] = n & 7;
    }

    for (int task = blockIdx.x; task < NTASKS; task += GRID_P) {
        const int rb = task >> 4, ck = task & 15, t0 = ck << 4;

        // Stage A tile + first B tile (both async), wait once.
        {
            const uint4* asrc = (const uint4*)(g_ah + (size_t)rb * BM * DDIM);
            #pragma unroll
            for (int i = tid; i < 1024; i += NTHR) {
                int r = i >> 3, c = i & 7;
                CP_ASYNC16(sb + 16384u + (uint32_t)(r * 128 + ((c ^ (r & 7)) << 4)),
                           asrc + i);
            }
            const uint4* bs = (const uint4*)(g_bh + (size_t)t0 * BN * DDIM);
            #pragma unroll
            for (int i = tid; i < 512; i += NTHR) {
                int r = i >> 3, c = i & 7;
                CP_ASYNC16(sb + (uint32_t)(r * 128 + ((c ^ (r & 7)) << 4)), bs + i);
            }
            CP_COMMIT();
        }
        CP_WAIT(0);
        __syncthreads();

        uint32_t afr[2][4][4];
        #pragma unroll
        for (int mi = 0; mi < 2; mi++)
            #pragma unroll
            for (int ks = 0; ks < 4; ks++) {
                int m  = wm * 32 + mi * 16 + (g & 1) * 8 + r8;
                int kc = ks * 2 + (g >> 1);
                uint32_t addr = sb + 16384u + (uint32_t)(m * 128 + ((kc ^ (m & 7)) << 4));
                LDSM_X4(afr[mi][ks][0], afr[mi][ks][1], afr[mi][ks][2], afr[mi][ks][3], addr);
            }

        float s[4] = {0.f, 0.f, 0.f, 0.f};
        uint32_t hacc[4] = {0u, 0u, 0u, 0u};

        #pragma unroll 1
        for (int it = 0; it < CHUNK; it++) {
            const int t = t0 + it;
            const uint32_t bufb = sb + (uint32_t)((it & 1) << 13);
            // Prefetch next tile into the other buffer. Safe: that buffer was
            // last READ in iteration it-1, fenced by the sync that ended it.
            if (it < CHUNK - 1) {
                const uint32_t nbuf = sb + (uint32_t)(((it + 1) & 1) << 13);
                const uint4* bs = (const uint4*)(g_bh + (size_t)(t + 1) * BN * DDIM);
                #pragma unroll
                for (int i = tid; i < 512; i += NTHR) {
                    int r = i >> 3, c = i & 7;
                    CP_ASYNC16(nbuf + (uint32_t)(r * 128 + ((c ^ (r & 7)) << 4)), bs + i);
                }
                CP_COMMIT();
            }

            // Accumulators pre-biased to -12: MMA yields logit-12 directly.
            uint32_t c_[2][4][2];
            #pragma unroll
            for (int mi = 0; mi < 2; mi++)
                #pragma unroll
                for (int ni = 0; ni < 4; ni++) {
                    c_[mi][ni][0] = BIAS_H2; c_[mi][ni][1] = BIAS_H2;
                }

            #pragma unroll
            for (int ks = 0; ks < 4; ks++) {
                uint32_t b[4][2];
                #pragma unroll
                for (int p = 0; p < 2; p++) {
                    uint32_t addr = bufb + brow[p] +
                                    (uint32_t)((((ks * 2 + kg) ^ bnlo[p])) << 4);
                    LDSM_X4(b[2 * p][0], b[2 * p][1], b[2 * p + 1][0], b[2 * p + 1][1], addr);
                }
                #pragma unroll
                for (int mi = 0; mi < 2; mi++)
                    #pragma unroll
                    for (int ni = 0; ni < 4; ni++)
                        MMA16816_F16(c_[mi][ni], afr[mi][ks], b[ni]);
            }

            // Diagonal capture: rows rb*128+[0,128) x cols t*64+[0,64)
            if ((t >> 1) == rb) {
                const int coff = (t & 1) << 6;
                #pragma unroll
                for (int mi = 0; mi < 2; mi++)
                    #pragma unroll
                    for (int ni = 0; ni < 4; ni++) {
                        float2 f0 = h2f(c_[mi][ni][0]);
                        float2 f1 = h2f(c_[mi][ni][1]);
                        int r0 = wm * 32 + mi * 16 + q, r1 = r0 + 8;
                        int cb = coff + wn * 32 + ni * 8 + 2 * p4;
                        if (r0 == cb)     g_pos[rb * BM + r0] = f0.x;
                        if (r0 == cb + 1) g_pos[rb * BM + r0] = f0.y;
                        if (r1 == cb)     g_pos[rb * BM + r1] = f1.x;
                        if (r1 == cb + 1) g_pos[rb * BM + r1] = f1.y;
                    }
            }

            // All-fp16 epilogue: ex2.f16x2 on raw MMA regs, HADD2 trees
            #pragma unroll
            for (int mi = 0; mi < 2; mi++)
                #pragma unroll
                for (int j = 0; j < 2; j++) {
                    uint32_t e0 = ex2_h2(c_[mi][0][j]);
                    uint32_t e1 = ex2_h2(c_[mi][1][j]);
                    uint32_t e2 = ex2_h2(c_[mi][2][j]);
                    uint32_t e3 = ex2_h2(c_[mi][3][j]);
                    uint32_t tsum = hadd2u(hadd2u(e0, e1), hadd2u(e2, e3));
                    hacc[mi * 2 + j] = hadd2u(hacc[mi * 2 + j], tsum);
                }
            if (it & 1) {                    // drain fp16 partials every 2 tiles
                #pragma unroll
                for (int slot = 0; slot < 4; slot++) {
                    float2 f = h2f(hacc[slot]);
                    s[slot] += f.x + f.y;
                    hacc[slot] = 0u;
                }
            }

            if (it < CHUNK - 1) {
                CP_WAIT(0);                 // next B tile resident
                __syncthreads();            // + all warps done reading bufb
            }
        }

        // Per-chunk row-sum reduction (overlay on buf0): [128][8]
        __syncthreads();                    // all warps done with buf1 reads
        float* red = (float*)smem;
        #pragma unroll
        for (int slot = 0; slot < 4; slot++) {
            int mi = slot >> 1, hi = slot & 1;
            int r = wm * 32 + mi * 16 + hi * 8 + q;
            red[r * 8 + wn * 4 + p4] = s[slot];
        }
        __syncthreads();
        if (tid < BM) {
            float tot = 0.f;
            #pragma unroll
            for (int i = 0; i < 8; i++) tot += red[tid * 8 + i];
            g_rowsum[ck * NROWS + rb * BM + tid] = tot;
        }
        __syncthreads();                    // red reads done before next task
    }
}

// ───────────── Kernel 3a: per-row LSE merge + block partials ────────────────
__global__ void finalize1_kernel() {
    __shared__ float sh[256];
    int tid = threadIdx.x;
    int r = blockIdx.x * 256 + tid;
    float sum = 0.f;
    #pragma unroll
    for (int ck = 0; ck < NCHUNKS; ck++) sum += g_rowsum[ck * NROWS + r];
    // both sum and pos carry the 2^-12 / -12 bias -> cancels exactly
    sh[tid] = (log2f(sum) - g_pos[r]) * LN2F;
    __syncthreads();
    #pragma unroll
    for (int off = 128; off; off >>= 1) {
        if (tid < off) sh[tid] += sh[tid + off];
        __syncthreads();
    }
    if (tid == 0) g_part1[blockIdx.x] = sh[0];
}

// ───────────── Kernel 3b: final scalar ──────────────────────────────────────
__global__ void finalize2_kernel(float* __restrict__ out) {
    __shared__ float sh[64];
    int tid = threadIdx.x;
    sh[tid] = g_part1[tid];
    __syncthreads();
    #pragma unroll
    for (int off = 32; off; off >>= 1) {
        if (tid < off) sh[tid] += sh[tid + off];
        __syncthreads();
    }
    if (tid == 0) out[0] = sh[0] * (1.0f / (float)NROWS);
}

// ────────────────────────────────────────────────────────────────────────────
extern "C" void kernel_launch(void* const* d_in, const int* in_sizes, int n_in,
                              void* d_out, int out_size) {
    const float* z1 = (const float*)d_in[0];
    const float* z2 = (const float*)d_in[1];
    float* out = (float*)d_out;

    normalize_kernel<<<2048, 256>>>(z1, z2);
    gemm_lse_kernel<<<GRID_P, NTHR>>>();
    finalize1_kernel<<<64, 256>>>();
    finalize2_kernel<<<1, 64>>>(out);
}

// round 10
// speedup vs baseline: 3.2239x; 1.0527x over previous
#include <cuda_runtime.h>
#include <cuda_fp16.h>
#include <cstdint>
#include <math.h>

#define NROWS 16384
#define DDIM  64
#define BM    128
#define BN    64
#define NTILES   (NROWS / BN)     // 256
#define CHUNK    16               // tiles per task
#define NCHUNKS  (NTILES / CHUNK) // 16 chunks per rowblock
#define NTASKS   ((NROWS / BM) * NCHUNKS)   // 2048
#define GRID_P   444
#define NTHR  256
#define SCALE_A 28.853900817779268f   // log2(e)/tau
#define LN2F    0.6931471805599453f
#define BIAS_H2 0xCA00CA00u           // packed half2(-12, -12)

__device__ __half g_ah[NROWS * DDIM];      // z1n * log2(e)/tau  [m][k]
__device__ __half g_bh[NROWS * DDIM];      // z2n               [n][k]
__device__ float  g_rowsum[NCHUNKS * NROWS];   // biased by 2^-12 (cancels)
__device__ float  g_pos[NROWS];                // biased logit (cancels)
__device__ float  g_part1[64];
__device__ unsigned g_task = 0;            // dynamic ticket (reset by normalize)
__device__ unsigned g_fin  = 0;            // finalize last-block counter

__device__ __forceinline__ uint32_t smem_u32(const void* p) {
    uint32_t a;
    asm("{ .reg .u64 t; cvta.to.shared.u64 t, %1; cvt.u32.u64 %0, t; }" : "=r"(a) : "l"(p));
    return a;
}
__device__ __forceinline__ uint32_t ex2_h2(uint32_t x) {
    uint32_t r; asm("ex2.approx.f16x2 %0, %1;" : "=r"(r) : "r"(x)); return r;
}
__device__ __forceinline__ uint32_t hadd2u(uint32_t a, uint32_t b) {
    uint32_t r; asm("add.rn.f16x2 %0, %1, %2;" : "=r"(r) : "r"(a), "r"(b)); return r;
}
__device__ __forceinline__ float2 h2f(uint32_t u) {
    __half2 h = *reinterpret_cast<__half2*>(&u);
    return __half22float2(h);
}
#define LDSM_X4(r0, r1, r2, r3, addr) \
    asm volatile("ldmatrix.sync.aligned.m8n8.x4.shared.b16 {%0,%1,%2,%3}, [%4];" \
        : "=r"(r0), "=r"(r1), "=r"(r2), "=r"(r3) : "r"(addr))
#define MMA16816_F16(d, a, b) \
    asm volatile("mma.sync.aligned.m16n8k16.row.col.f16.f16.f16.f16 " \
        "{%0,%1}, {%2,%3,%4,%5}, {%6,%7}, {%0,%1};" \
        : "+r"((d)[0]), "+r"((d)[1]) \
        : "r"((a)[0]), "r"((a)[1]), "r"((a)[2]), "r"((a)[3]), "r"((b)[0]), "r"((b)[1]))
#define CP_ASYNC16(dst, src) \
    asm volatile("cp.async.cg.shared.global [%0], [%1], 16;" :: "r"(dst), "l"(src))
#define CP_COMMIT()  asm volatile("cp.async.commit_group;" ::: "memory")
#define CP_WAIT(n)   asm volatile("cp.async.wait_group %0;" :: "n"(n) : "memory")

// ─────────────── Kernel 1: L2-normalize + fp16 quantize + scale fold ────────
__global__ void normalize_kernel(const float* __restrict__ z1,
                                 const float* __restrict__ z2) {
    if (blockIdx.x == 0 && threadIdx.x == 0) g_task = 0;   // reset ticket

    int warp = blockIdx.x * (blockDim.x >> 5) + (threadIdx.x >> 5);
    int lane = threadIdx.x & 31;
    int row  = warp * 2 + (lane >> 4);
    int l16  = lane & 15;

    const float* src; __half* dst; float scale; int r;
    if (row < NROWS) { src = z1; dst = g_ah; r = row;          scale = SCALE_A; }
    else             { src = z2; dst = g_bh; r = row - NROWS;  scale = 1.0f;    }

    float4 v = ((const float4*)(src + (size_t)r * DDIM))[l16];
    float ss = v.x * v.x + v.y * v.y + v.z * v.z + v.w * v.w;
    #pragma unroll
    for (int off = 8; off; off >>= 1)
        ss += __shfl_xor_sync(0xffffffffu, ss, off);
    float inv = scale / fmaxf(sqrtf(ss), 1e-12f);
    __half2 h0 = __floats2half2_rn(v.x * inv, v.y * inv);
    __half2 h1 = __floats2half2_rn(v.z * inv, v.w * inv);
    uint2 o = make_uint2(*(uint32_t*)&h0, *(uint32_t*)&h1);
    ((uint2*)(dst + (size_t)r * DDIM))[l16] = o;
}

// ── Kernel 2: persistent fp16 GEMM, dynamic tickets, 3 CTAs/SM ─────────────
// smem: B buf0 [0,8K), B buf1 [8K,16K), A stage [16K,32K)
__global__ void __launch_bounds__(NTHR, 3) gemm_lse_kernel() {
    __shared__ __align__(128) char smem[32768];
    __shared__ int s_task;
    const uint32_t sb = smem_u32(smem);
    const int tid = threadIdx.x, lane = tid & 31, w = tid >> 5;
    const int wm = w >> 1, wn = w & 1;          // 4x2 warp grid, 32x32 tiles
    const int g = lane >> 3, r8 = lane & 7;
    const int kg = g & 1;
    const int q = lane >> 2, p4 = lane & 3;

    uint32_t brow[2]; int bnlo[2];
    #pragma unroll
    for (int p = 0; p < 2; p++) {
        int n = wn * 32 + p * 16 + (g >> 1) * 8 + r8;
        brow[p] = (uint32_t)(n * 128);
        bnlo[p] = n & 7;
    }

    for (;;) {
        if (tid == 0) s_task = (int)atomicAdd(&g_task, 1u);
        __syncthreads();
        const int task = s_task;
        if (task >= NTASKS) break;
        const int rb = task >> 4, ck = task & 15, t0 = ck << 4;

        // Stage A tile + first B tile (both async), wait once.
        {
            const uint4* asrc = (const uint4*)(g_ah + (size_t)rb * BM * DDIM);
            #pragma unroll
            for (int i = tid; i < 1024; i += NTHR) {
                int r = i >> 3, c = i & 7;
                CP_ASYNC16(sb + 16384u + (uint32_t)(r * 128 + ((c ^ (r & 7)) << 4)),
                           asrc + i);
            }
            const uint4* bs = (const uint4*)(g_bh + (size_t)t0 * BN * DDIM);
            #pragma unroll
            for (int i = tid; i < 512; i += NTHR) {
                int r = i >> 3, c = i & 7;
                CP_ASYNC16(sb + (uint32_t)(r * 128 + ((c ^ (r & 7)) << 4)), bs + i);
            }
            CP_COMMIT();
        }
        CP_WAIT(0);
        __syncthreads();

        uint32_t afr[2][4][4];
        #pragma unroll
        for (int mi = 0; mi < 2; mi++)
            #pragma unroll
            for (int ks = 0; ks < 4; ks++) {
                int m  = wm * 32 + mi * 16 + (g & 1) * 8 + r8;
                int kc = ks * 2 + (g >> 1);
                uint32_t addr = sb + 16384u + (uint32_t)(m * 128 + ((kc ^ (m & 7)) << 4));
                LDSM_X4(afr[mi][ks][0], afr[mi][ks][1], afr[mi][ks][2], afr[mi][ks][3], addr);
            }

        float s[4] = {0.f, 0.f, 0.f, 0.f};
        uint32_t hacc[4] = {0u, 0u, 0u, 0u};

        #pragma unroll 1
        for (int it = 0; it < CHUNK; it++) {
            const int t = t0 + it;
            const uint32_t bufb = sb + (uint32_t)((it & 1) << 13);
            // Prefetch next tile into the other buffer (fenced by prior sync).
            if (it < CHUNK - 1) {
                const uint32_t nbuf = sb + (uint32_t)(((it + 1) & 1) << 13);
                const uint4* bs = (const uint4*)(g_bh + (size_t)(t + 1) * BN * DDIM);
                #pragma unroll
                for (int i = tid; i < 512; i += NTHR) {
                    int r = i >> 3, c = i & 7;
                    CP_ASYNC16(nbuf + (uint32_t)(r * 128 + ((c ^ (r & 7)) << 4)), bs + i);
                }
                CP_COMMIT();
            }

            // Accumulators pre-biased to -12: MMA yields logit-12 directly.
            uint32_t c_[2][4][2];
            #pragma unroll
            for (int mi = 0; mi < 2; mi++)
                #pragma unroll
                for (int ni = 0; ni < 4; ni++) {
                    c_[mi][ni][0] = BIAS_H2; c_[mi][ni][1] = BIAS_H2;
                }

            #pragma unroll
            for (int ks = 0; ks < 4; ks++) {
                uint32_t b[4][2];
                #pragma unroll
                for (int p = 0; p < 2; p++) {
                    uint32_t addr = bufb + brow[p] +
                                    (uint32_t)((((ks * 2 + kg) ^ bnlo[p])) << 4);
                    LDSM_X4(b[2 * p][0], b[2 * p][1], b[2 * p + 1][0], b[2 * p + 1][1], addr);
                }
                #pragma unroll
                for (int mi = 0; mi < 2; mi++)
                    #pragma unroll
                    for (int ni = 0; ni < 4; ni++)
                        MMA16816_F16(c_[mi][ni], afr[mi][ks], b[ni]);
            }

            // Diagonal capture: rows rb*128+[0,128) x cols t*64+[0,64)
            if ((t >> 1) == rb) {
                const int coff = (t & 1) << 6;
                #pragma unroll
                for (int mi = 0; mi < 2; mi++)
                    #pragma unroll
                    for (int ni = 0; ni < 4; ni++) {
                        float2 f0 = h2f(c_[mi][ni][0]);
                        float2 f1 = h2f(c_[mi][ni][1]);
                        int r0 = wm * 32 + mi * 16 + q, r1 = r0 + 8;
                        int cb = coff + wn * 32 + ni * 8 + 2 * p4;
                        if (r0 == cb)     g_pos[rb * BM + r0] = f0.x;
                        if (r0 == cb + 1) g_pos[rb * BM + r0] = f0.y;
                        if (r1 == cb)     g_pos[rb * BM + r1] = f1.x;
                        if (r1 == cb + 1) g_pos[rb * BM + r1] = f1.y;
                    }
            }

            // All-fp16 epilogue: ex2.f16x2 on raw MMA regs, HADD2 trees
            #pragma unroll
            for (int mi = 0; mi < 2; mi++)
                #pragma unroll
                for (int j = 0; j < 2; j++) {
                    uint32_t e0 = ex2_h2(c_[mi][0][j]);
                    uint32_t e1 = ex2_h2(c_[mi][1][j]);
                    uint32_t e2 = ex2_h2(c_[mi][2][j]);
                    uint32_t e3 = ex2_h2(c_[mi][3][j]);
                    uint32_t tsum = hadd2u(hadd2u(e0, e1), hadd2u(e2, e3));
                    hacc[mi * 2 + j] = hadd2u(hacc[mi * 2 + j], tsum);
                }
            if (it & 1) {                    // drain fp16 partials every 2 tiles
                #pragma unroll
                for (int slot = 0; slot < 4; slot++) {
                    float2 f = h2f(hacc[slot]);
                    s[slot] += f.x + f.y;
                    hacc[slot] = 0u;
                }
            }

            if (it < CHUNK - 1) {
                CP_WAIT(0);                 // next B tile resident
                __syncthreads();            // + all warps done reading bufb
            }
        }

        // Per-chunk row-sum reduction (overlay on buf0): [128][8]
        __syncthreads();                    // all warps done with buf1 reads
        float* red = (float*)smem;
        #pragma unroll
        for (int slot = 0; slot < 4; slot++) {
            int mi = slot >> 1, hi = slot & 1;
            int r = wm * 32 + mi * 16 + hi * 8 + q;
            red[r * 8 + wn * 4 + p4] = s[slot];
        }
        __syncthreads();
        if (tid < BM) {
            float tot = 0.f;
            #pragma unroll
            for (int i = 0; i < 8; i++) tot += red[tid * 8 + i];
            g_rowsum[ck * NROWS + rb * BM + tid] = tot;
        }
        __syncthreads();                    // red reads done before next task
    }
}

// ───────── Kernel 3: per-row LSE merge; last block does the final reduce ────
__global__ void finalize_kernel(float* __restrict__ out) {
    __shared__ float sh[256];
    int tid = threadIdx.x;
    int r = blockIdx.x * 256 + tid;
    float sum = 0.f;
    #pragma unroll
    for (int ck = 0; ck < NCHUNKS; ck++) sum += g_rowsum[ck * NROWS + r];
    // both sum and pos carry the 2^-12 / -12 bias -> cancels exactly
    sh[tid] = (log2f(sum) - g_pos[r]) * LN2F;
    __syncthreads();
    #pragma unroll
    for (int off = 128; off; off >>= 1) {
        if (tid < off) sh[tid] += sh[tid + off];
        __syncthreads();
    }
    int amLast = 0;
    if (tid == 0) {
        g_part1[blockIdx.x] = sh[0];
        __threadfence();
        amLast = (atomicAdd(&g_fin, 1u) == 63u);
    }
    amLast = __syncthreads_or(amLast);
    if (amLast) {
        if (tid == 0) g_fin = 0;           // reset for next graph replay
        if (tid < 64) sh[tid] = g_part1[tid];
        __syncthreads();
        if (tid == 0) {
            float tot = 0.f;
            #pragma unroll
            for (int i = 0; i < 64; i++) tot += sh[i];   // fixed order
            out[0] = tot * (1.0f / (float)NROWS);
        }
    }
}

// ────────────────────────────────────────────────────────────────────────────
extern "C" void kernel_launch(void* const* d_in, const int* in_sizes, int n_in,
                              void* d_out, int out_size) {
    const float* z1 = (const float*)d_in[0];
    const float* z2 = (const float*)d_in[1];
    float* out = (float*)d_out;

    normalize_kernel<<<2048, 256>>>(z1, z2);
    gemm_lse_kernel<<<GRID_P, NTHR>>>();
    finalize_kernel<<<64, 256>>>(out);
}